// round 16
// baseline (speedup 1.0000x reference)
#include <cuda_runtime.h>

#define BB 32
#define NN 16384
#define PP 4096
#define CC 14
#define TPB 512
#define PTS 8
#define SEGS (NN / (TPB * PTS))          // 4 dist segments per batch
#define NBLK (BB * SEGS)                 // 128 blocks: one SM each, perfectly balanced
#define CBB SEGS                         // all 4 blocks per batch do centroid work
#define NW (TPB / 32)                    // 16 warps

// all zero-initialized at module load; every replay restores them
__device__ unsigned g_count;             // global arrivals (flat, 128)
__device__ unsigned g_bcnt[BB];          // per-batch centroid arrivals (to 4)
__device__ float    g_sums[BB][CC * 4];  // float4-aligned per class
__device__ float    g_part[NBLK];

__device__ __forceinline__ float smooth_l1(float x) {
    const float ax = fabsf(x);
    return (ax < 1.0f) ? (0.5f * x * x) : (ax - 0.5f);
}
__device__ __forceinline__ float sqrt_fast(float x) {
    float r; asm("sqrt.approx.f32 %0, %1;" : "=f"(r) : "f"(x)); return r;
}
__device__ __forceinline__ unsigned ld_acq(const unsigned* p) {
    unsigned v;
    asm volatile("ld.acquire.gpu.u32 %0, [%1];" : "=r"(v) : "l"(p) : "memory");
    return v;
}
__device__ __forceinline__ unsigned atom_inc_acqrel(unsigned* p) {
    unsigned old;
    asm volatile("atom.acq_rel.gpu.add.u32 %0, [%1], %2;"
                 : "=r"(old) : "l"(p), "r"(1u) : "memory");
    return old;
}

__global__ void __launch_bounds__(TPB) k_fused(
        const float* __restrict__ disp, const float* __restrict__ sub,
        const float* __restrict__ cpred, const float* __restrict__ origin,
        const int* __restrict__ tgt, float* __restrict__ out)
{
    const int bid = blockIdx.x;
    const int tid = threadIdx.x;
    const int lane = tid & 31, wid = tid >> 5;
    const int b = bid / SEGS;
    const int seg = bid % SEGS;

    __shared__ float red[NW][64];
    __shared__ float s_cgx[CC], s_cgy[CC], s_cgz[CC];
    __shared__ float4 s_c[CC];
    __shared__ float wsum[NW];
    __shared__ double dsum[NW];
    __shared__ int s_win;

    const float* __restrict__ dp = disp + (size_t)b * NN;
    const float* __restrict__ sx = sub + (size_t)b * 3 * NN;
    const float* __restrict__ sy = sx + NN;
    const float* __restrict__ sz = sx + 2 * NN;
    const int segbase = seg * (TPB * PTS);       // 4096 floats per array

    // ====== L2 prefetch of this block's dist tile (64 KB, 1 line/thread) ======
    {
        const int aid = tid >> 7;                // 0..3 -> which array
        const int off = (tid & 127) << 5;        // 128 lines x 32 floats
        const float* p = dp;
        if (aid == 1) p = sx; else if (aid == 2) p = sy; else if (aid == 3) p = sz;
        asm volatile("prefetch.global.L2 [%0];" :: "l"(p + segbase + off));
    }

    // ================= phase 1: centroids (ALL blocks, 2 pts/thread) =================
    {
        const int base = seg * (PP / CBB);            // 1024 points per block
        const float* __restrict__ ox = origin + (size_t)b * 9 * PP + base;
        const float* __restrict__ oy = ox + PP;
        const float* __restrict__ oz = ox + 2 * PP;
        const int* __restrict__ tg = tgt + (size_t)b * PP + base;

        const int2 c2   = *(const int2*)(tg + tid * 2);
        const float2 x2 = *(const float2*)(ox + tid * 2);
        const float2 y2 = *(const float2*)(oy + tid * 2);
        const float2 z2 = *(const float2*)(oz + tid * 2);

        // padded bins: [class*4 + comp]; point 0 initializes via SEL, point 1 adds
        float v[64];
        #pragma unroll
        for (int cc = 0; cc < CC; cc++) {
            const bool e0 = (c2.x == cc);
            v[cc * 4 + 0] = e0 ? x2.x : 0.0f;
            v[cc * 4 + 1] = e0 ? y2.x : 0.0f;
            v[cc * 4 + 2] = e0 ? z2.x : 0.0f;
            v[cc * 4 + 3] = e0 ? 1.0f : 0.0f;
        }
        #pragma unroll
        for (int k = CC * 4; k < 64; k++) v[k] = 0.0f;   // pad for reduce-scatter
        #pragma unroll
        for (int cc = 0; cc < CC; cc++) {
            if (c2.y == cc) {              // predicated FADDs
                v[cc * 4 + 0] += x2.y;
                v[cc * 4 + 1] += y2.y;
                v[cc * 4 + 2] += z2.y;
                v[cc * 4 + 3] += 1.0f;
            }
        }

        // reduce-scatter: 5 exchange levels; lane l ends owning totals 2l, 2l+1
        #pragma unroll
        for (int off = 16, cnt = 64; off >= 1; off >>= 1, cnt >>= 1) {
            const int half = cnt >> 1;
            const bool hi = (lane & off) != 0;
            #pragma unroll
            for (int i = 0; i < 32; i++) {
                if (i < half) {
                    const float send = hi ? v[i] : v[i + half];
                    const float recv = __shfl_xor_sync(0xFFFFFFFFu, send, off);
                    const float keep = hi ? v[i + half] : v[i];
                    v[i] = keep + recv;
                }
            }
        }
        if (lane < 28) {
            red[wid][2 * lane]     = v[0];
            red[wid][2 * lane + 1] = v[1];
        }
        __syncthreads();
        if (tid < CC * 4) {
            float s = 0.0f;
            #pragma unroll
            for (int w = 0; w < NW; w++) s += red[w][tid];
            atomicAdd(&g_sums[b][tid], s);   // relaxed; published by acq_rel below
        }
        __syncthreads();
        if (tid == 0)
            (void)atom_inc_acqrel(&g_bcnt[b]);     // arrive
    }

    // ================= phase 2: distance loss (all blocks) =================
    {
        const int o0 = segbase + tid * 4;
        const int o1 = o0 + TPB * 4;

        // issue all loads + ||p||^2 BEFORE the poll (L2-resident via prefetch)
        const float4 dA = *(const float4*)(dp + o0);
        const float4 dB = *(const float4*)(dp + o1);
        const float4 xA = *(const float4*)(sx + o0);
        const float4 xB = *(const float4*)(sx + o1);
        const float4 yA = *(const float4*)(sy + o0);
        const float4 yB = *(const float4*)(sy + o1);
        const float4 zA = *(const float4*)(sz + o0);
        const float4 zB = *(const float4*)(sz + o1);

        const float xs[8] = {xA.x, xA.y, xA.z, xA.w, xB.x, xB.y, xB.z, xB.w};
        const float ys[8] = {yA.x, yA.y, yA.z, yA.w, yB.x, yB.y, yB.z, yB.w};
        const float zs[8] = {zA.x, zA.y, zA.z, zA.w, zB.x, zB.y, zB.z, zB.w};
        const float ds[8] = {dA.x, dA.y, dA.z, dA.w, dB.x, dB.y, dB.z, dB.w};
        float pn[8];
        #pragma unroll
        for (int k = 0; k < 8; k++)
            pn[k] = fmaf(xs[k], xs[k], fmaf(ys[k], ys[k], zs[k] * zs[k]));

        // per-warp autonomous poll (whole warp loads one address: 1 txn/iter)
        while (ld_acq(&g_bcnt[b]) < CBB) __nanosleep(32);

        // every warp finalizes centroids (duplicate stores of identical values)
        if (lane < CC) {
            const float4 f = *(const float4*)&g_sums[b][lane * 4];
            const float inv = 1.0f / fmaxf(f.w, 1.0f);
            const float x = f.x * inv, y = f.y * inv, z = f.z * inv;
            s_cgx[lane] = x; s_cgy[lane] = y; s_cgz[lane] = z;
            s_c[lane] = make_float4(-2.0f * x, -2.0f * y, -2.0f * z,
                                    fmaf(x, x, fmaf(y, y, z * z)));
        }
        __syncwarp();

        float tmin[8];
        #pragma unroll
        for (int k = 0; k < 8; k++) tmin[k] = 3.4e38f;
        #pragma unroll
        for (int c = 0; c < CC; c++) {
            const float4 cp = s_c[c];
            #pragma unroll
            for (int k = 0; k < 8; k++) {
                const float t = fmaf(xs[k], cp.x, fmaf(ys[k], cp.y, fmaf(zs[k], cp.z, cp.w)));
                tmin[k] = fminf(tmin[k], t);
            }
        }
        float local = 0.0f;
        #pragma unroll
        for (int k = 0; k < 8; k++) {
            const float d2 = fmaxf(pn[k] + tmin[k], 0.0f);
            local += smooth_l1(ds[k] - sqrt_fast(d2));
        }

        #pragma unroll
        for (int off = 16; off > 0; off >>= 1)
            local += __shfl_xor_sync(0xFFFFFFFFu, local, off);
        if (lane == 0) wsum[wid] = local;

        // chamfer + separation: seg==0 block, warp 0 only (tail-filled)
        float extra = 0.0f;
        if (seg == 0 && tid < 32) {
            float cl = 0.0f;
            if (tid < CC) {
                const float* __restrict__ cp = cpred + (size_t)b * 3 * CC;
                const float qx = cp[tid], qy = cp[CC + tid], qz = cp[2 * CC + tid];
                float rmin = 3.4e38f, m1 = 3.4e38f, m2 = 3.4e38f;
                #pragma unroll
                for (int j = 0; j < CC; j++) {
                    const float dx = qx - s_cgx[j], dy = qy - s_cgy[j], dz = qz - s_cgz[j];
                    const float d2 = fmaf(dx, dx, fmaf(dy, dy, dz * dz));
                    rmin = fminf(rmin, d2);
                    const float dd = sqrt_fast(d2);
                    if (dd < m1) { m2 = m1; m1 = dd; }
                    else if (dd < m2) { m2 = dd; }
                }
                const float gx = s_cgx[tid], gy = s_cgy[tid], gz = s_cgz[tid];
                float cmin = 3.4e38f;
                #pragma unroll
                for (int i = 0; i < CC; i++) {
                    const float dx = cp[i] - gx, dy = cp[CC + i] - gy, dz = cp[2 * CC + i] - gz;
                    cmin = fminf(cmin, fmaf(dx, dx, fmaf(dy, dy, dz * dz)));
                }
                cl = rmin + cmin + 0.1f * (m1 / m2);
            }
            #pragma unroll
            for (int off = 16; off > 0; off >>= 1)
                cl += __shfl_xor_sync(0xFFFFFFFFu, cl, off);
            if (tid == 0) extra = cl;
        }
        __syncthreads();          // all wsum[] stores visible to tid 0

        if (tid == 0) {
            float v2 = extra;
            #pragma unroll
            for (int w = 0; w < NW; w++) v2 += wsum[w];
            g_part[bid] = v2;                                  // plain store
            s_win = (atom_inc_acqrel(&g_count) == NBLK - 1);   // release publishes it
        }
        __syncthreads();

        if (s_win) {
            // 128 partials; threads 128..511 contribute zero
            double dv = (tid < NBLK) ? (double)g_part[tid] : 0.0;
            #pragma unroll
            for (int off = 16; off > 0; off >>= 1)
                dv += __shfl_xor_sync(0xFFFFFFFFu, dv, off);
            if (lane == 0) dsum[wid] = dv;
            __syncthreads();
            if (tid == 0) {
                double tot = 0.0;
                #pragma unroll
                for (int w = 0; w < NW; w++) tot += dsum[w];
                out[0] = (float)tot;
                g_count = 0;                 // reset for next replay
            }
            if (tid < BB) g_bcnt[tid] = 0;   // reset per-batch counters
            // reset g_sums (32*56 = 1792 floats, 512 threads)
            float* gs = &g_sums[0][0];
            for (int i = tid; i < BB * CC * 4; i += TPB) gs[i] = 0.0f;
        }
    }
}

extern "C" void kernel_launch(void* const* d_in, const int* in_sizes, int n_in,
                              void* d_out, int out_size) {
    const float* disp   = (const float*)d_in[0];       // [B, N]
    const float* sub    = (const float*)d_in[1];       // [B, 3, N]
    const float* cpred  = (const float*)d_in[2];       // [B, 3, C]
    const float* origin = (const float*)d_in[3];       // [B, 9, P]
    const int*   tg     = (const int*)d_in[4];         // [B, P]
    float* out = (float*)d_out;

    k_fused<<<NBLK, TPB>>>(disp, sub, cpred, origin, tg, out);
}

// round 17
// speedup vs baseline: 1.1600x; 1.1600x over previous
#include <cuda_runtime.h>

#define BB 32
#define NN 16384
#define PP 4096
#define CC 14
// ---- k1: centroid binning ----
#define T1 512
#define S1 4                              // 4 segments per batch
#define NB1 (BB * S1)                     // 128 blocks
// ---- k2: distance loss ----
#define T2 256
#define PTS 8
#define S2 (NN / (T2 * PTS))              // 8 segments per batch
#define NB2 (BB * S2)                     // 256 blocks
#define NW2 (T2 / 32)

// zero-initialized at module load; winner of k2 restores every replay
__device__ unsigned g_count;
__device__ float    g_sums[BB][CC * 4];   // float4-aligned per class
__device__ float    g_part[NB2];

__device__ __forceinline__ float smooth_l1(float x) {
    const float ax = fabsf(x);
    return (ax < 1.0f) ? (0.5f * x * x) : (ax - 0.5f);
}
__device__ __forceinline__ float sqrt_fast(float x) {
    float r; asm("sqrt.approx.f32 %0, %1;" : "=f"(r) : "f"(x)); return r;
}
__device__ __forceinline__ unsigned atom_inc_acqrel(unsigned* p) {
    unsigned old;
    asm volatile("atom.acq_rel.gpu.add.u32 %0, [%1], %2;"
                 : "=r"(old) : "l"(p), "r"(1u) : "memory");
    return old;
}

// ==================== k1: per-batch class sums (no protocol) ====================
__global__ void __launch_bounds__(T1) k_cent(const float* __restrict__ origin,
                                             const int* __restrict__ tgt)
{
    const int bid = blockIdx.x;
    const int tid = threadIdx.x;
    const int lane = tid & 31, wid = tid >> 5;
    const int b = bid / S1;
    const int seg = bid % S1;

    __shared__ float red[T1 / 32][64];

    const int base = seg * (PP / S1);             // 1024 points per block
    const float* __restrict__ ox = origin + (size_t)b * 9 * PP + base;
    const float* __restrict__ oy = ox + PP;
    const float* __restrict__ oz = ox + 2 * PP;
    const int* __restrict__ tg = tgt + (size_t)b * PP + base;

    const int2 c2   = *(const int2*)(tg + tid * 2);
    const float2 x2 = *(const float2*)(ox + tid * 2);
    const float2 y2 = *(const float2*)(oy + tid * 2);
    const float2 z2 = *(const float2*)(oz + tid * 2);

    // padded bins: point 0 initializes via SEL, point 1 adds
    float v[64];
    #pragma unroll
    for (int cc = 0; cc < CC; cc++) {
        const bool e0 = (c2.x == cc);
        v[cc * 4 + 0] = e0 ? x2.x : 0.0f;
        v[cc * 4 + 1] = e0 ? y2.x : 0.0f;
        v[cc * 4 + 2] = e0 ? z2.x : 0.0f;
        v[cc * 4 + 3] = e0 ? 1.0f : 0.0f;
    }
    #pragma unroll
    for (int k = CC * 4; k < 64; k++) v[k] = 0.0f;
    #pragma unroll
    for (int cc = 0; cc < CC; cc++) {
        if (c2.y == cc) {
            v[cc * 4 + 0] += x2.y;
            v[cc * 4 + 1] += y2.y;
            v[cc * 4 + 2] += z2.y;
            v[cc * 4 + 3] += 1.0f;
        }
    }

    // reduce-scatter: lane l ends owning padded bins 2l, 2l+1
    #pragma unroll
    for (int off = 16, cnt = 64; off >= 1; off >>= 1, cnt >>= 1) {
        const int half = cnt >> 1;
        const bool hi = (lane & off) != 0;
        #pragma unroll
        for (int i = 0; i < 32; i++) {
            if (i < half) {
                const float send = hi ? v[i] : v[i + half];
                const float recv = __shfl_xor_sync(0xFFFFFFFFu, send, off);
                const float keep = hi ? v[i + half] : v[i];
                v[i] = keep + recv;
            }
        }
    }
    if (lane < 28) {
        red[wid][2 * lane]     = v[0];
        red[wid][2 * lane + 1] = v[1];
    }
    __syncthreads();
    if (tid < CC * 4) {
        float s = 0.0f;
        #pragma unroll
        for (int w = 0; w < T1 / 32; w++) s += red[w][tid];
        atomicAdd(&g_sums[b][tid], s);     // kernel boundary publishes
    }
}

// ==================== k2: distance + chamfer + final reduce ====================
__global__ void __launch_bounds__(T2) k_dist(const float* __restrict__ disp,
                                             const float* __restrict__ sub,
                                             const float* __restrict__ cpred,
                                             float* __restrict__ out)
{
    const int bid = blockIdx.x;
    const int tid = threadIdx.x;
    const int lane = tid & 31, wid = tid >> 5;
    const int b = bid / S2;
    const int seg = bid % S2;

    __shared__ float s_cgx[CC], s_cgy[CC], s_cgz[CC];
    __shared__ float4 s_c[CC];
    __shared__ float wsum[NW2];
    __shared__ double dsum[NW2];
    __shared__ int s_win;

    const float* __restrict__ dp = disp + (size_t)b * NN;
    const float* __restrict__ sx = sub + (size_t)b * 3 * NN;
    const float* __restrict__ sy = sx + NN;
    const float* __restrict__ sz = sx + 2 * NN;
    const int o0 = seg * (T2 * PTS) + tid * 4;
    const int o1 = o0 + T2 * 4;

    // issue all dist loads immediately (no protocol in front of them)
    const float4 dA = *(const float4*)(dp + o0);
    const float4 dB = *(const float4*)(dp + o1);
    const float4 xA = *(const float4*)(sx + o0);
    const float4 xB = *(const float4*)(sx + o1);
    const float4 yA = *(const float4*)(sy + o0);
    const float4 yB = *(const float4*)(sy + o1);
    const float4 zA = *(const float4*)(sz + o0);
    const float4 zB = *(const float4*)(sz + o1);

    // centroids: g_sums is ready (kernel dependency) — finalize per warp
    if (lane < CC) {
        const float4 f = *(const float4*)&g_sums[b][lane * 4];
        const float inv = 1.0f / fmaxf(f.w, 1.0f);
        const float x = f.x * inv, y = f.y * inv, z = f.z * inv;
        s_cgx[lane] = x; s_cgy[lane] = y; s_cgz[lane] = z;
        s_c[lane] = make_float4(-2.0f * x, -2.0f * y, -2.0f * z,
                                fmaf(x, x, fmaf(y, y, z * z)));
    }
    __syncwarp();

    const float xs[8] = {xA.x, xA.y, xA.z, xA.w, xB.x, xB.y, xB.z, xB.w};
    const float ys[8] = {yA.x, yA.y, yA.z, yA.w, yB.x, yB.y, yB.z, yB.w};
    const float zs[8] = {zA.x, zA.y, zA.z, zA.w, zB.x, zB.y, zB.z, zB.w};
    const float ds[8] = {dA.x, dA.y, dA.z, dA.w, dB.x, dB.y, dB.z, dB.w};
    float pn[8];
    #pragma unroll
    for (int k = 0; k < 8; k++)
        pn[k] = fmaf(xs[k], xs[k], fmaf(ys[k], ys[k], zs[k] * zs[k]));

    float tmin[8];
    #pragma unroll
    for (int k = 0; k < 8; k++) tmin[k] = 3.4e38f;
    #pragma unroll
    for (int c = 0; c < CC; c++) {
        const float4 cp = s_c[c];
        #pragma unroll
        for (int k = 0; k < 8; k++) {
            const float t = fmaf(xs[k], cp.x, fmaf(ys[k], cp.y, fmaf(zs[k], cp.z, cp.w)));
            tmin[k] = fminf(tmin[k], t);
        }
    }
    float local = 0.0f;
    #pragma unroll
    for (int k = 0; k < 8; k++) {
        const float d2 = fmaxf(pn[k] + tmin[k], 0.0f);
        local += smooth_l1(ds[k] - sqrt_fast(d2));
    }

    #pragma unroll
    for (int off = 16; off > 0; off >>= 1)
        local += __shfl_xor_sync(0xFFFFFFFFu, local, off);
    if (lane == 0) wsum[wid] = local;

    // chamfer + separation: seg==0 block, warp 0 only
    float extra = 0.0f;
    if (seg == 0 && tid < 32) {
        float cl = 0.0f;
        if (tid < CC) {
            const float* __restrict__ cp = cpred + (size_t)b * 3 * CC;
            const float qx = cp[tid], qy = cp[CC + tid], qz = cp[2 * CC + tid];
            float rmin = 3.4e38f, m1 = 3.4e38f, m2 = 3.4e38f;
            #pragma unroll
            for (int j = 0; j < CC; j++) {
                const float dx = qx - s_cgx[j], dy = qy - s_cgy[j], dz = qz - s_cgz[j];
                const float d2 = fmaf(dx, dx, fmaf(dy, dy, dz * dz));
                rmin = fminf(rmin, d2);
                const float dd = sqrt_fast(d2);
                if (dd < m1) { m2 = m1; m1 = dd; }
                else if (dd < m2) { m2 = dd; }
            }
            const float gx = s_cgx[tid], gy = s_cgy[tid], gz = s_cgz[tid];
            float cmin = 3.4e38f;
            #pragma unroll
            for (int i = 0; i < CC; i++) {
                const float dx = cp[i] - gx, dy = cp[CC + i] - gy, dz = cp[2 * CC + i] - gz;
                cmin = fminf(cmin, fmaf(dx, dx, fmaf(dy, dy, dz * dz)));
            }
            cl = rmin + cmin + 0.1f * (m1 / m2);
        }
        #pragma unroll
        for (int off = 16; off > 0; off >>= 1)
            cl += __shfl_xor_sync(0xFFFFFFFFu, cl, off);
        if (tid == 0) extra = cl;
    }
    __syncthreads();

    if (tid == 0) {
        float v2 = extra;
        #pragma unroll
        for (int w = 0; w < NW2; w++) v2 += wsum[w];
        g_part[bid] = v2;                                  // plain store
        s_win = (atom_inc_acqrel(&g_count) == NB2 - 1);    // release publishes it
    }
    __syncthreads();

    if (s_win) {
        double dv = (double)g_part[tid];
        #pragma unroll
        for (int off = 16; off > 0; off >>= 1)
            dv += __shfl_xor_sync(0xFFFFFFFFu, dv, off);
        if (lane == 0) dsum[wid] = dv;
        __syncthreads();
        if (tid == 0) {
            double tot = 0.0;
            #pragma unroll
            for (int w = 0; w < NW2; w++) tot += dsum[w];
            out[0] = (float)tot;
            g_count = 0;                     // reset for next replay
        }
        // reset g_sums for next replay (k1 accumulates into zeros)
        float* gs = &g_sums[0][0];
        #pragma unroll
        for (int i = tid; i < BB * CC * 4; i += T2) gs[i] = 0.0f;
    }
}

extern "C" void kernel_launch(void* const* d_in, const int* in_sizes, int n_in,
                              void* d_out, int out_size) {
    const float* disp   = (const float*)d_in[0];       // [B, N]
    const float* sub    = (const float*)d_in[1];       // [B, 3, N]
    const float* cpred  = (const float*)d_in[2];       // [B, 3, C]
    const float* origin = (const float*)d_in[3];       // [B, 9, P]
    const int*   tg     = (const int*)d_in[4];         // [B, P]
    float* out = (float*)d_out;

    k_cent<<<NB1, T1>>>(origin, tg);
    k_dist<<<NB2, T2>>>(disp, sub, cpred, out);
}